// round 5
// baseline (speedup 1.0000x reference)
#include <cuda_runtime.h>

// AdaptiveSudokuLoss: ce + 0.5 * constraint + 0.1 * entropy, fused single kernel.
// outputs: (B, 81, 9) fp32, targets: (B, 81) int32, out: scalar fp32.
//
// R4: L1-wavefront-bound fix. Each block stages an 8-batch tile of logits into
// smem via coalesced float4 loads (23 wf/batch vs ~205 for scattered LDG.32),
// computes per-cell softmax from smem (stride-9 LDS, conflict-free), writes
// probs back in place, then does the 27 constraint sums per batch element.
// Fused deterministic final reduction via threadfence + ticket.

#define THREADS 256
#define GTILE 8                 // batch elements per block iteration
#define TILE_FLOATS (GTILE * 729)
#define GRID 740                // 5 blocks/SM * 148 SMs = one resident wave

__device__ float g_ce[GRID];
__device__ float g_cons[GRID];
__device__ float g_conf[GRID];
__device__ unsigned int g_count = 0;

__global__ __launch_bounds__(THREADS)
void sudoku_loss_fused(const float* __restrict__ outp,
                       const int* __restrict__ tgt,
                       int Bn,
                       float* __restrict__ d_out)
{
    __shared__ float sraw[TILE_FLOATS];   // raw logits, overwritten by probs
    __shared__ float wr[8][3];
    __shared__ bool is_last;

    const int tid = threadIdx.x;
    const int ntiles = (Bn + GTILE - 1) / GTILE;

    float ce_acc = 0.f, cons_acc = 0.f, conf_acc = 0.f;

    for (int t = blockIdx.x; t < ntiles; t += gridDim.x) {
        const int b0 = t * GTILE;
        const int nvalid = (Bn - b0 < GTILE) ? (Bn - b0) : GTILE;
        const int nfloats = nvalid * 729;
        const int n4 = nfloats >> 2;

        // ---- phase 0: cooperative coalesced float4 stage gmem -> smem -------
        {
            const float4* __restrict__ src =
                (const float4*)(outp + (size_t)b0 * 729);
            float4* __restrict__ dst = (float4*)sraw;
            #pragma unroll 2
            for (int i = tid; i < n4; i += THREADS) dst[i] = src[i];
            const int rem = nfloats & 3;
            if (tid < rem)
                sraw[n4 * 4 + tid] = outp[(size_t)b0 * 729 + n4 * 4 + tid];
        }
        __syncthreads();

        // ---- phase 1: per-cell softmax from smem; probs back in place -------
        const int ncells = nvalid * 81;
        for (int cell = tid; cell < ncells; cell += THREADS) {
            float v[9];
            #pragma unroll
            for (int j = 0; j < 9; j++) v[j] = sraw[cell * 9 + j];

            float m = v[0];
            #pragma unroll
            for (int j = 1; j < 9; j++) m = fmaxf(m, v[j]);

            float e[9];
            float s = 0.f;
            #pragma unroll
            for (int j = 0; j < 9; j++) { e[j] = __expf(v[j] - m); s += e[j]; }

            const float inv = __frcp_rn(s);
            float sx = 0.f;
            #pragma unroll
            for (int j = 0; j < 9; j++) {
                const float p = e[j] * inv;
                sraw[cell * 9 + j] = p;
                sx = fmaf(p, v[j], sx);
            }
            const float lse = m + __logf(s);

            const int tv = tgt[(size_t)b0 * 81 + cell];
            float xt = 0.f;
            #pragma unroll
            for (int j = 0; j < 9; j++) xt += (j == tv) ? v[j] : 0.f;

            ce_acc   += lse - xt;    // -logp[target]
            conf_acc += lse - sx;    // entropy
        }
        __syncthreads();

        // ---- phase 2: 27 constraint sums; item = (bl, idx, digit) -----------
        for (int it = tid; it < ncells; it += THREADS) {
            const int bl  = it / 81;
            const int rem = it - bl * 81;
            const int idx = rem / 9;
            const int d   = rem - idx * 9;
            const float* __restrict__ p = sraw + bl * 729;

            float rs = 0.f, cs = 0.f, bs = 0.f;
            #pragma unroll
            for (int c = 0; c < 9; c++) rs += p[(idx * 9 + c) * 9 + d];
            #pragma unroll
            for (int r = 0; r < 9; r++) cs += p[(r * 9 + idx) * 9 + d];
            const int br = idx / 3, bc = idx - br * 3;
            #pragma unroll
            for (int dr = 0; dr < 3; dr++)
                #pragma unroll
                for (int dc = 0; dc < 3; dc++)
                    bs += p[((br * 3 + dr) * 9 + (bc * 3 + dc)) * 9 + d];

            rs -= 1.f; cs -= 1.f; bs -= 1.f;
            cons_acc += rs * rs + cs * cs + bs * bs;
        }
        __syncthreads();   // smem reused next tile
    }

    // ---- block reduction: 3 scalars over 8 warps ----------------------------
    #pragma unroll
    for (int o = 16; o > 0; o >>= 1) {
        ce_acc   += __shfl_down_sync(0xffffffffu, ce_acc,   o);
        cons_acc += __shfl_down_sync(0xffffffffu, cons_acc, o);
        conf_acc += __shfl_down_sync(0xffffffffu, conf_acc, o);
    }
    const int wid = tid >> 5, lid = tid & 31;
    if (lid == 0) { wr[wid][0] = ce_acc; wr[wid][1] = cons_acc; wr[wid][2] = conf_acc; }
    __syncthreads();

    if (tid == 0) {
        float a = 0.f, b = 0.f, c = 0.f;
        #pragma unroll
        for (int w = 0; w < 8; w++) { a += wr[w][0]; b += wr[w][1]; c += wr[w][2]; }
        g_ce[blockIdx.x]   = a;
        g_cons[blockIdx.x] = b;
        g_conf[blockIdx.x] = c;
        __threadfence();
        const unsigned ticket = atomicAdd(&g_count, 1u);
        is_last = (ticket == gridDim.x - 1);
        if (is_last) g_count = 0;           // reset for graph replay
    }
    __syncthreads();

    // ---- last block: deterministic final reduce + combine -------------------
    if (is_last) {
        float a = 0.f, b = 0.f, c = 0.f;
        for (int i = tid; i < (int)gridDim.x; i += THREADS) {
            a += g_ce[i]; b += g_cons[i]; c += g_conf[i];
        }
        #pragma unroll
        for (int o = 16; o > 0; o >>= 1) {
            a += __shfl_down_sync(0xffffffffu, a, o);
            b += __shfl_down_sync(0xffffffffu, b, o);
            c += __shfl_down_sync(0xffffffffu, c, o);
        }
        if (lid == 0) { wr[wid][0] = a; wr[wid][1] = b; wr[wid][2] = c; }
        __syncthreads();
        if (tid == 0) {
            float fa = 0.f, fb = 0.f, fc = 0.f;
            #pragma unroll
            for (int w = 0; w < 8; w++) { fa += wr[w][0]; fb += wr[w][1]; fc += wr[w][2]; }
            const float Ncells = (float)Bn * 81.0f;
            d_out[0] = fa / Ncells
                     + 0.5f * fb / ((float)Bn * 9.0f * 27.0f)
                     + 0.1f * fc / (Ncells + 1e-8f);
        }
    }
}

extern "C" void kernel_launch(void* const* d_in, const int* in_sizes, int n_in,
                              void* d_out, int out_size)
{
    const float* outp = (const float*)d_in[0];   // (B, 81, 9) fp32
    const int*   tgt  = (const int*)d_in[1];     // (B, 81) int32
    float*       out  = (float*)d_out;

    const int Bn = in_sizes[0] / (81 * 9);
    sudoku_loss_fused<<<GRID, THREADS>>>(outp, tgt, Bn, out);
}

// round 8
// speedup vs baseline: 1.0999x; 1.0999x over previous
#include <cuda_runtime.h>

// AdaptiveSudokuLoss: ce + 0.5 * constraint + 0.1 * entropy, fused single kernel.
// outputs: (B, 81, 9) fp32, targets: (B, 81) int32, out: scalar fp32.
//
// R7 (= R6 resubmission after infra failure). Block = 192 threads, 7 batch
// elements per tile.
// Phase 1: thread-per-cell softmax (scattered LDG, probs -> padded smem rows
//          of 84 words: 16B-aligned + odd quad-stride = conflict-free LDS.128).
// Phase 2: 27 units/batch (9 rows, 9 cols, 9 boxes), each unit computes all 9
//          digit sums. 63 units of each type over 7 batches -> homogeneous
//          warps (0,1=rows via float4, 2,3=cols, 4,5=boxes). Fused ticket
//          final reduction.

#define THREADS 192
#define GTILE 7
#define ROWSTRIDE 84                  // words per sudoku row (81 + 3 pad)
#define BATCHSTRIDE (9 * ROWSTRIDE)   // 756 words per batch element
#define GRID 1480                     // 10 blocks/SM * 148 SMs

__device__ float g_ce[GRID];
__device__ float g_cons[GRID];
__device__ float g_conf[GRID];
__device__ unsigned int g_count = 0;

__global__ __launch_bounds__(THREADS)
void sudoku_loss_fused(const float* __restrict__ outp,
                       const int* __restrict__ tgt,
                       int Bn,
                       float* __restrict__ d_out)
{
    __shared__ __align__(16) float sp[GTILE * BATCHSTRIDE];
    __shared__ float wr[6][3];
    __shared__ bool is_last;

    const int tid = threadIdx.x;
    const int ntiles = (Bn + GTILE - 1) / GTILE;

    float ce_acc = 0.f, cons_acc = 0.f, conf_acc = 0.f;

    for (int t = blockIdx.x; t < ntiles; t += gridDim.x) {
        const int b0 = t * GTILE;
        const int nvalid = (Bn - b0 < GTILE) ? (Bn - b0) : GTILE;
        const int ncells = nvalid * 81;

        // ---- phase 1: per-cell softmax; probs -> padded smem ----------------
        for (int cell = tid; cell < ncells; cell += THREADS) {
            const int bl = cell / 81;
            const int q  = cell - bl * 81;          // r*9 + c
            const int r  = q / 9;
            const int c  = q - r * 9;
            const float* __restrict__ x = outp + ((size_t)(b0 + bl) * 81 + q) * 9;

            float v[9];
            #pragma unroll
            for (int j = 0; j < 9; j++) v[j] = x[j];

            float m = v[0];
            #pragma unroll
            for (int j = 1; j < 9; j++) m = fmaxf(m, v[j]);

            float e[9];
            float s = 0.f;
            #pragma unroll
            for (int j = 0; j < 9; j++) { e[j] = __expf(v[j] - m); s += e[j]; }

            const float inv = __frcp_rn(s);
            float sx = 0.f;
            float* __restrict__ dst = sp + bl * BATCHSTRIDE + r * ROWSTRIDE + c * 9;
            #pragma unroll
            for (int j = 0; j < 9; j++) {
                const float p = e[j] * inv;
                dst[j] = p;
                sx = fmaf(p, v[j], sx);
            }
            const float lse = m + __logf(s);

            const int tv = tgt[(size_t)(b0 + bl) * 81 + q];
            float xt = 0.f;
            #pragma unroll
            for (int j = 0; j < 9; j++) xt += (j == tv) ? v[j] : 0.f;

            ce_acc   += lse - xt;    // -logp[target]
            conf_acc += lse - sx;    // entropy
        }
        __syncthreads();

        // ---- phase 2: 27 units per batch, homogeneous warps ----------------
        const int wtype = tid >> 6;          // 0=rows, 1=cols, 2=boxes
        const int u     = tid & 63;          // unit id within type, 63 valid
        const int bl    = u / 9;
        const int idx   = u - bl * 9;

        if (u < 63 && bl < nvalid) {
            float s[9];
            #pragma unroll
            for (int d = 0; d < 9; d++) s[d] = -1.f;

            const float* __restrict__ base = sp + bl * BATCHSTRIDE;

            if (wtype == 0) {
                // row idx: 81 contiguous floats -> 20 float4 + 1 scalar
                const float4* __restrict__ rp =
                    (const float4*)(base + idx * ROWSTRIDE);
                #pragma unroll
                for (int k = 0; k < 20; k++) {
                    const float4 v = rp[k];
                    s[(4 * k + 0) % 9] += v.x;
                    s[(4 * k + 1) % 9] += v.y;
                    s[(4 * k + 2) % 9] += v.z;
                    s[(4 * k + 3) % 9] += v.w;
                }
                s[8] += base[idx * ROWSTRIDE + 80];
            } else if (wtype == 1) {
                // col idx: 9 cells, 9 contiguous digits each
                #pragma unroll
                for (int r = 0; r < 9; r++) {
                    const float* __restrict__ cp = base + r * ROWSTRIDE + idx * 9;
                    #pragma unroll
                    for (int d = 0; d < 9; d++) s[d] += cp[d];
                }
            } else {
                // box idx: 3 row-fragments of 27 contiguous floats
                const int br = idx / 3, bc = idx - br * 3;
                #pragma unroll
                for (int i = 0; i < 3; i++) {
                    const float* __restrict__ bp =
                        base + (3 * br + i) * ROWSTRIDE + 27 * bc;
                    #pragma unroll
                    for (int k = 0; k < 27; k++) s[k % 9] += bp[k];
                }
            }

            #pragma unroll
            for (int d = 0; d < 9; d++) cons_acc = fmaf(s[d], s[d], cons_acc);
        }
        __syncthreads();   // smem reused next tile
    }

    // ---- block reduction: 3 scalars over 6 warps ----------------------------
    #pragma unroll
    for (int o = 16; o > 0; o >>= 1) {
        ce_acc   += __shfl_down_sync(0xffffffffu, ce_acc,   o);
        cons_acc += __shfl_down_sync(0xffffffffu, cons_acc, o);
        conf_acc += __shfl_down_sync(0xffffffffu, conf_acc, o);
    }
    const int wid = tid >> 5, lid = tid & 31;
    if (lid == 0) { wr[wid][0] = ce_acc; wr[wid][1] = cons_acc; wr[wid][2] = conf_acc; }
    __syncthreads();

    if (tid == 0) {
        float a = 0.f, b = 0.f, c = 0.f;
        #pragma unroll
        for (int w = 0; w < 6; w++) { a += wr[w][0]; b += wr[w][1]; c += wr[w][2]; }
        g_ce[blockIdx.x]   = a;
        g_cons[blockIdx.x] = b;
        g_conf[blockIdx.x] = c;
        __threadfence();
        const unsigned ticket = atomicAdd(&g_count, 1u);
        is_last = (ticket == gridDim.x - 1);
        if (is_last) g_count = 0;           // reset for graph replay
    }
    __syncthreads();

    // ---- last block: deterministic final reduce + combine -------------------
    if (is_last) {
        float a = 0.f, b = 0.f, c = 0.f;
        for (int i = tid; i < (int)gridDim.x; i += THREADS) {
            a += g_ce[i]; b += g_cons[i]; c += g_conf[i];
        }
        #pragma unroll
        for (int o = 16; o > 0; o >>= 1) {
            a += __shfl_down_sync(0xffffffffu, a, o);
            b += __shfl_down_sync(0xffffffffu, b, o);
            c += __shfl_down_sync(0xffffffffu, c, o);
        }
        if (lid == 0) { wr[wid][0] = a; wr[wid][1] = b; wr[wid][2] = c; }
        __syncthreads();
        if (tid == 0) {
            float fa = 0.f, fb = 0.f, fc = 0.f;
            #pragma unroll
            for (int w = 0; w < 6; w++) { fa += wr[w][0]; fb += wr[w][1]; fc += wr[w][2]; }
            const float Ncells = (float)Bn * 81.0f;
            d_out[0] = fa / Ncells
                     + 0.5f * fb / ((float)Bn * 9.0f * 27.0f)
                     + 0.1f * fc / (Ncells + 1e-8f);
        }
    }
}

extern "C" void kernel_launch(void* const* d_in, const int* in_sizes, int n_in,
                              void* d_out, int out_size)
{
    const float* outp = (const float*)d_in[0];   // (B, 81, 9) fp32
    const int*   tgt  = (const int*)d_in[1];     // (B, 81) int32
    float*       out  = (float*)d_out;

    const int Bn = in_sizes[0] / (81 * 9);
    sudoku_loss_fused<<<GRID, THREADS>>>(outp, tgt, Bn, out);
}